// round 9
// baseline (speedup 1.0000x reference)
#include <cuda_runtime.h>
#include <cuda_bf16.h>
#include <cstdint>

// R9: mma.sync bf16 split-2. 512 threads (16 warps = 4 row-groups x 4
// col-quarters, warp tile 16x64) -> per-thread acc halves to 32 regs,
// fits the 64-reg cap of launch_bounds(512,2) -> 32 warps/SM.
// Deep cp.async pipeline (2 slabs in flight, wait-depth 1), fused leaf
// embedder (blockdiag(We,We)), single-CTA tail kernel for levels 6..0.

static __forceinline__ __device__ float lrelu(float v) { return v > 0.0f ? v : 0.01f * v; }

constexpr int DEPTH = 18;
constexpr int THREADS = 512;
// smem byte map
constexpr int SA_HI = 0;        // [64][264] bf16
constexpr int SA_LO = 33792;
constexpr int W_ST  = 67584;    // 2 slots x 16896
constexpr int SB1   = 101376;   // 1024
constexpr int SB2   = 102400;   // 512
constexpr int SBE   = 102912;   // 512
constexpr int SMEM_LVL = 103424;

// prepped split weights (row-major bf16)
__device__ __align__(16) __nv_bfloat16 W1hi_d[65536];   // [256][256]
__device__ __align__(16) __nv_bfloat16 W1lo_d[65536];
__device__ __align__(16) __nv_bfloat16 W2hi_d[32768];   // [256][128]
__device__ __align__(16) __nv_bfloat16 W2lo_d[32768];
__device__ __align__(16) __nv_bfloat16 WBhi_d[16384];   // blockdiag(We,We) [64][256]
__device__ __align__(16) __nv_bfloat16 WBlo_d[16384];

static __forceinline__ __device__ uint32_t smem_u32(const void* p) {
    uint32_t a;
    asm("{ .reg .u64 t; cvta.to.shared.u64 t, %1; cvt.u32.u64 %0, t; }" : "=r"(a) : "l"(p));
    return a;
}
static __forceinline__ __device__ void cp16(uint32_t d, const void* s) {
    asm volatile("cp.async.cg.shared.global [%0], [%1], 16;" :: "r"(d), "l"(s));
}
#define CP_COMMIT() asm volatile("cp.async.commit_group;" ::: "memory")
#define CP_WAIT(N)  asm volatile("cp.async.wait_group %0;" :: "n"(N) : "memory")

static __forceinline__ __device__ void ldsm4(unsigned* r, uint32_t a) {
    asm volatile("ldmatrix.sync.aligned.m8n8.x4.shared.b16 {%0,%1,%2,%3}, [%4];"
                 : "=r"(r[0]), "=r"(r[1]), "=r"(r[2]), "=r"(r[3]) : "r"(a));
}
static __forceinline__ __device__ void ldsm4t(unsigned* r, uint32_t a) {
    asm volatile("ldmatrix.sync.aligned.m8n8.x4.trans.shared.b16 {%0,%1,%2,%3}, [%4];"
                 : "=r"(r[0]), "=r"(r[1]), "=r"(r[2]), "=r"(r[3]) : "r"(a));
}
static __forceinline__ __device__ void mma_bf16(float* c, const unsigned* a, const unsigned* b) {
    asm volatile("mma.sync.aligned.m16n8k16.row.col.f32.bf16.bf16.f32 "
                 "{%0,%1,%2,%3}, {%4,%5,%6,%7}, {%8,%9}, {%0,%1,%2,%3};"
                 : "+f"(c[0]), "+f"(c[1]), "+f"(c[2]), "+f"(c[3])
                 : "r"(a[0]), "r"(a[1]), "r"(a[2]), "r"(a[3]), "r"(b[0]), "r"(b[1]));
}
static __forceinline__ __device__ void split2(float h0, float h1,
                                              __nv_bfloat162& hi, __nv_bfloat162& lo) {
    hi = __floats2bfloat162_rn(h0, h1);
    lo = __floats2bfloat162_rn(h0 - __bfloat162float(hi.x), h1 - __bfloat162float(hi.y));
}

__global__ void prep_kernel(const float* __restrict__ W1, const float* __restrict__ W2,
                            const float* __restrict__ We) {
    int t = blockIdx.x * 256 + threadIdx.x;
    if (t < 65536) {
        float f = W1[t];
        __nv_bfloat16 hi = __float2bfloat16(f);
        W1hi_d[t] = hi; W1lo_d[t] = __float2bfloat16(f - __bfloat162float(hi));
    }
    if (t < 32768) {
        float f = W2[t];
        __nv_bfloat16 hi = __float2bfloat16(f);
        W2hi_d[t] = hi; W2lo_d[t] = __float2bfloat16(f - __bfloat162float(hi));
    }
    if (t < 16384) {                       // WB[k][c], k<64, c<256
        int k = t >> 8, c = t & 255;
        float f = 0.0f;
        if (k < 32 && c < 128)   f = We[k * 128 + c];
        if (k >= 32 && c >= 128) f = We[(k - 32) * 128 + (c - 128)];
        __nv_bfloat16 hi = __float2bfloat16(f);
        WBhi_d[t] = hi; WBlo_d[t] = __float2bfloat16(f - __bfloat162float(hi));
    }
}

// slab loader. Slab id g: LEAF schedule 0..35, plain 0..31.
template<bool LEAF>
static __forceinline__ __device__ void load_slab(int g, uint32_t base, int tid) {
    uint32_t slot = base + W_ST + (uint32_t)(g & 1) * 16896u;
    const char *hi, *lo;
    bool k256;
    if (LEAF) {
        if (g < 4)       { hi = (const char*)WBhi_d + (size_t)g * 8192;        lo = (const char*)WBlo_d + (size_t)g * 8192;        k256 = true; }
        else if (g < 20) { hi = (const char*)W1hi_d + (size_t)(g - 4) * 8192;  lo = (const char*)W1lo_d + (size_t)(g - 4) * 8192;  k256 = true; }
        else             { hi = (const char*)W2hi_d + (size_t)(g - 20) * 4096; lo = (const char*)W2lo_d + (size_t)(g - 20) * 4096; k256 = false; }
    } else {
        if (g < 16)      { hi = (const char*)W1hi_d + (size_t)g * 8192;        lo = (const char*)W1lo_d + (size_t)g * 8192;        k256 = true; }
        else             { hi = (const char*)W2hi_d + (size_t)(g - 16) * 4096; lo = (const char*)W2lo_d + (size_t)(g - 16) * 4096; k256 = false; }
    }
    if (k256) {
        #pragma unroll
        for (int j = 0; j < 2; ++j) {
            int idx = tid + j * THREADS;             // 1024 chunks of 16B
            int part = idx >> 9, rc = idx & 511, r = rc >> 5, c = rc & 31;
            cp16(slot + part * 8448 + r * 528 + c * 16, (part ? lo : hi) + r * 512 + c * 16);
        }
    } else {
        int idx = tid;                               // 512 chunks
        int part = idx >> 8, rc = idx & 255, r = rc >> 4, c = rc & 15;
        cp16(slot + part * 4352 + r * 272 + c * 16, (part ? lo : hi) + r * 256 + c * 16);
    }
    CP_COMMIT();
}

template<bool LEAF>
__global__ void __launch_bounds__(THREADS, 2)
level_kernel(const float* __restrict__ X, float* __restrict__ Y,
             float* __restrict__ Yemb,
             const float* __restrict__ b1, const float* __restrict__ b2,
             const float* __restrict__ be, int n)
{
    extern __shared__ __align__(16) char sm[];
    const uint32_t base = smem_u32(sm);
    const int tid = threadIdx.x, wid = tid >> 5, lane = tid & 31;
    const int rg = wid >> 2, nq = wid & 3;
    const int wr = rg * 16;
    const int row0 = blockIdx.x * 64;
    const int lrow = lane & 15, lcol8 = (lane >> 4) * 8;
    const int qr = lane >> 2, qc = (lane & 3) * 2;

    constexpr int G = LEAF ? 36 : 32;
    constexpr int EPI1_AT = LEAF ? 20 : 16;

    load_slab<LEAF>(0, base, tid);
    load_slab<LEAF>(1, base, tid);

    if (tid < 256) ((float*)(sm + SB1))[tid] = b1[tid];
    if (tid < 128) ((float*)(sm + SB2))[tid] = b2[tid];
    if (tid < 128) ((float*)(sm + SBE))[tid] = be[tid];

    // A tile load + split. LEAF: A' [64][64] (2 leaves/row); else X [64][256].
    if (LEAF) {
        const float* Xb = X + (size_t)row0 * 64;
        for (int idx = tid; idx < 64 * 16; idx += THREADS) {
            int r = idx >> 4, c4 = idx & 15;
            float4 v = make_float4(0.f, 0.f, 0.f, 0.f);
            if (row0 + r < n) v = reinterpret_cast<const float4*>(Xb)[r * 16 + c4];
            __nv_bfloat162 h0, l0, h1, l1;
            split2(v.x, v.y, h0, l0); split2(v.z, v.w, h1, l1);
            uint32_t off = (uint32_t)r * 528 + c4 * 8;
            *(__nv_bfloat162*)(sm + SA_HI + off)     = h0;
            *(__nv_bfloat162*)(sm + SA_HI + off + 4) = h1;
            *(__nv_bfloat162*)(sm + SA_LO + off)     = l0;
            *(__nv_bfloat162*)(sm + SA_LO + off + 4) = l1;
        }
    } else {
        for (int idx = tid; idx < 64 * 64; idx += THREADS) {
            int r = idx >> 6, c4 = idx & 63;
            float4 v = make_float4(0.f, 0.f, 0.f, 0.f);
            if (row0 + r < n) v = reinterpret_cast<const float4*>(X)[(size_t)(row0 + r) * 64 + c4];
            __nv_bfloat162 h0, l0, h1, l1;
            split2(v.x, v.y, h0, l0); split2(v.z, v.w, h1, l1);
            uint32_t off = (uint32_t)r * 528 + c4 * 8;
            *(__nv_bfloat162*)(sm + SA_HI + off)     = h0;
            *(__nv_bfloat162*)(sm + SA_HI + off + 4) = h1;
            *(__nv_bfloat162*)(sm + SA_LO + off)     = l0;
            *(__nv_bfloat162*)(sm + SA_LO + off + 4) = l1;
        }
    }

    const float* sB1 = (const float*)(sm + SB1);
    const float* sB2 = (const float*)(sm + SB2);
    const float* sBE = (const float*)(sm + SBE);

    float accA[8][4];   // emb(leaf)/layer1: warp 16 x 64 (cols nq*64..)
    float accB[4][4];   // layer2: warp 16 x 32 (cols nq*32..)
    #pragma unroll
    for (int t = 0; t < 8; ++t) {
        int c = nq * 64 + t * 8 + qc;
        float v0 = LEAF ? sBE[c & 127] : sB1[c];
        float v1 = LEAF ? sBE[(c + 1) & 127] : sB1[c + 1];
        accA[t][0] = v0; accA[t][1] = v1; accA[t][2] = v0; accA[t][3] = v1;
    }

    const uint32_t aH0 = base + SA_HI + (uint32_t)(wr + lrow) * 528;
    const uint32_t aL0 = base + SA_LO + (uint32_t)(wr + lrow) * 528;

    for (int g = 0; g < G; ++g) {
        // Epilogues at stage top (prev stage ended with a full sync; the
        // CP_WAIT+sync below publishes sA writes before any warp reads them).
        if (LEAF && g == 4) {
            #pragma unroll
            for (int t = 0; t < 8; ++t) {
                int c = nq * 64 + t * 8 + qc;
                int r = wr + qr;
                float v0 = lrelu(accA[t][0]), v1 = lrelu(accA[t][1]);
                float v2 = lrelu(accA[t][2]), v3 = lrelu(accA[t][3]);
                __nv_bfloat162 hi2, lo2;
                split2(v0, v1, hi2, lo2);
                *(__nv_bfloat162*)(sm + SA_HI + r * 528 + c * 2) = hi2;
                *(__nv_bfloat162*)(sm + SA_LO + r * 528 + c * 2) = lo2;
                if (row0 + r < n)
                    *reinterpret_cast<float2*>(Yemb + (size_t)(row0 + r) * 256 + c) = make_float2(v0, v1);
                split2(v2, v3, hi2, lo2);
                *(__nv_bfloat162*)(sm + SA_HI + (r + 8) * 528 + c * 2) = hi2;
                *(__nv_bfloat162*)(sm + SA_LO + (r + 8) * 528 + c * 2) = lo2;
                if (row0 + r + 8 < n)
                    *reinterpret_cast<float2*>(Yemb + (size_t)(row0 + r + 8) * 256 + c) = make_float2(v2, v3);
            }
            #pragma unroll
            for (int t = 0; t < 8; ++t) {
                int c = nq * 64 + t * 8 + qc;
                accA[t][0] = sB1[c]; accA[t][1] = sB1[c + 1];
                accA[t][2] = sB1[c]; accA[t][3] = sB1[c + 1];
            }
        }
        if (g == EPI1_AT) {
            #pragma unroll
            for (int t = 0; t < 8; ++t) {
                int c = nq * 64 + t * 8 + qc;
                int r = wr + qr;
                __nv_bfloat162 hi2, lo2;
                split2(lrelu(accA[t][0]), lrelu(accA[t][1]), hi2, lo2);
                *(__nv_bfloat162*)(sm + SA_HI + r * 528 + c * 2) = hi2;
                *(__nv_bfloat162*)(sm + SA_LO + r * 528 + c * 2) = lo2;
                split2(lrelu(accA[t][2]), lrelu(accA[t][3]), hi2, lo2);
                *(__nv_bfloat162*)(sm + SA_HI + (r + 8) * 528 + c * 2) = hi2;
                *(__nv_bfloat162*)(sm + SA_LO + (r + 8) * 528 + c * 2) = lo2;
            }
            #pragma unroll
            for (int t = 0; t < 4; ++t) {
                int c = nq * 32 + t * 8 + qc;
                accB[t][0] = sB2[c]; accB[t][1] = sB2[c + 1];
                accB[t][2] = sB2[c]; accB[t][3] = sB2[c + 1];
            }
        }

        if (g + 1 < G) { CP_WAIT(1); } else { CP_WAIT(0); }
        __syncthreads();

        int k0;
        if (LEAF) k0 = (g < 4) ? g * 16 : (g < 20 ? (g - 4) * 16 : (g - 20) * 16);
        else      k0 = (g < 16) ? g * 16 : (g - 16) * 16;
        const uint32_t slot = base + W_ST + (uint32_t)(g & 1) * 16896u;

        unsigned ah[4], al[4];
        ldsm4(ah, aH0 + (uint32_t)(k0 + lcol8) * 2);
        ldsm4(al, aL0 + (uint32_t)(k0 + lcol8) * 2);

        if (g < EPI1_AT) {                                  // K256 phase
            uint32_t brow = slot + (uint32_t)lrow * 528;
            #pragma unroll
            for (int p = 0; p < 4; ++p) {
                int nb = nq * 64 + p * 16;
                unsigned bh[4], bl[4];
                ldsm4t(bh, brow + (uint32_t)(nb + lcol8) * 2);
                ldsm4t(bl, brow + 8448 + (uint32_t)(nb + lcol8) * 2);
                mma_bf16(accA[2 * p],     ah, bh);
                mma_bf16(accA[2 * p + 1], ah, bh + 2);
                mma_bf16(accA[2 * p],     al, bh);
                mma_bf16(accA[2 * p + 1], al, bh + 2);
                mma_bf16(accA[2 * p],     ah, bl);
                mma_bf16(accA[2 * p + 1], ah, bl + 2);
            }
        } else {                                            // K128 phase (layer 2)
            uint32_t brow = slot + (uint32_t)lrow * 272;
            #pragma unroll
            for (int p = 0; p < 2; ++p) {
                int nb = nq * 32 + p * 16;
                unsigned bh[4], bl[4];
                ldsm4t(bh, brow + (uint32_t)(nb + lcol8) * 2);
                ldsm4t(bl, brow + 4352 + (uint32_t)(nb + lcol8) * 2);
                mma_bf16(accB[2 * p],     ah, bh);
                mma_bf16(accB[2 * p + 1], ah, bh + 2);
                mma_bf16(accB[2 * p],     al, bh);
                mma_bf16(accB[2 * p + 1], al, bh + 2);
                mma_bf16(accB[2 * p],     ah, bl);
                mma_bf16(accB[2 * p + 1], ah, bl + 2);
            }
        }
        __syncthreads();
        if (g + 2 < G) load_slab<LEAF>(g + 2, base, tid);   // deep prefetch
    }

    // final epilogue: Y = lrelu(accB)
    #pragma unroll
    for (int t = 0; t < 4; ++t) {
        int c = nq * 32 + t * 8 + qc;
        int r = row0 + wr + qr;
        if (r < n)
            *reinterpret_cast<float2*>(Y + (size_t)r * 128 + c) =
                make_float2(lrelu(accB[t][0]), lrelu(accB[t][1]));
        if (r + 8 < n)
            *reinterpret_cast<float2*>(Y + (size_t)(r + 8) * 128 + c) =
                make_float2(lrelu(accB[t][2]), lrelu(accB[t][3]));
    }
}

// Tail: levels 6..0 in one single-CTA kernel. Level output is re-packed in
// smem as next level's A (parent row = r>>1, col = (r&1)*128 + c).
__global__ void __launch_bounds__(THREADS, 1)
tail_kernel(float* __restrict__ out,
            const float* __restrict__ b1, const float* __restrict__ b2)
{
    extern __shared__ __align__(16) char sm[];
    const uint32_t base = smem_u32(sm);
    const int tid = threadIdx.x, wid = tid >> 5, lane = tid & 31;
    const int rg = wid >> 2, nq = wid & 3;
    const int wr = rg * 16;
    const int lrow = lane & 15, lcol8 = (lane >> 4) * 8;
    const int qr = lane >> 2, qc = (lane & 3) * 2;

    load_slab<false>(0, base, tid);
    load_slab<false>(1, base, tid);

    if (tid < 256) ((float*)(sm + SB1))[tid] = b1[tid];
    if (tid < 128) ((float*)(sm + SB2))[tid] = b2[tid];

    // initial A = children of level-6 parents: nodes 127..254 -> [64][256]
    {
        const float* X = out + 127 * 128;
        for (int idx = tid; idx < 64 * 64; idx += THREADS) {
            int r = idx >> 6, c4 = idx & 63;
            float4 v = reinterpret_cast<const float4*>(X)[r * 64 + c4];
            __nv_bfloat162 h0, l0, h1, l1;
            split2(v.x, v.y, h0, l0); split2(v.z, v.w, h1, l1);
            uint32_t off = (uint32_t)r * 528 + c4 * 8;
            *(__nv_bfloat162*)(sm + SA_HI + off)     = h0;
            *(__nv_bfloat162*)(sm + SA_HI + off + 4) = h1;
            *(__nv_bfloat162*)(sm + SA_LO + off)     = l0;
            *(__nv_bfloat162*)(sm + SA_LO + off + 4) = l1;
        }
    }

    const float* sB1 = (const float*)(sm + SB1);
    const float* sB2 = (const float*)(sm + SB2);

    float accA[8][4], accB[4][4];
    #pragma unroll
    for (int t = 0; t < 8; ++t) {
        int c = nq * 64 + t * 8 + qc;
        accA[t][0] = sB1[c]; accA[t][1] = sB1[c + 1];
        accA[t][2] = sB1[c]; accA[t][3] = sB1[c + 1];
    }

    const uint32_t aH0 = base + SA_HI + (uint32_t)(wr + lrow) * 528;
    const uint32_t aL0 = base + SA_LO + (uint32_t)(wr + lrow) * 528;

    int n = 64;
    constexpr int GT = 7 * 32;
    for (int g = 0; g < GT; ++g) {
        const int ph = g & 31;
        if (ph == 0 && g > 0) {
            // level (7 - g/32) finished: store Y, build next A, reset accA
            const int lvDone = 7 - (g >> 5);
            float* Y = out + (((size_t)1 << lvDone) - 1) * 128;
            #pragma unroll
            for (int t = 0; t < 4; ++t) {
                int c = nq * 32 + t * 8 + qc;
                #pragma unroll
                for (int h = 0; h < 2; ++h) {
                    int r = wr + qr + h * 8;
                    float v0 = lrelu(accB[t][2 * h]);
                    float v1 = lrelu(accB[t][2 * h + 1]);
                    if (r < n)
                        *reinterpret_cast<float2*>(Y + (size_t)r * 128 + c) = make_float2(v0, v1);
                    __nv_bfloat162 hi2, lo2;
                    split2(v0, v1, hi2, lo2);
                    uint32_t off = (uint32_t)(r >> 1) * 528 + ((r & 1) * 128 + c) * 2;
                    *(__nv_bfloat162*)(sm + SA_HI + off) = hi2;
                    *(__nv_bfloat162*)(sm + SA_LO + off) = lo2;
                }
            }
            #pragma unroll
            for (int t = 0; t < 8; ++t) {
                int c = nq * 64 + t * 8 + qc;
                accA[t][0] = sB1[c]; accA[t][1] = sB1[c + 1];
                accA[t][2] = sB1[c]; accA[t][3] = sB1[c + 1];
            }
            n >>= 1;
        }
        if (ph == 16) {
            #pragma unroll
            for (int t = 0; t < 8; ++t) {
                int c = nq * 64 + t * 8 + qc;
                int r = wr + qr;
                __nv_bfloat162 hi2, lo2;
                split2(lrelu(accA[t][0]), lrelu(accA[t][1]), hi2, lo2);
                *(__nv_bfloat162*)(sm + SA_HI + r * 528 + c * 2) = hi2;
                *(__nv_bfloat162*)(sm + SA_LO + r * 528 + c * 2) = lo2;
                split2(lrelu(accA[t][2]), lrelu(accA[t][3]), hi2, lo2);
                *(__nv_bfloat162*)(sm + SA_HI + (r + 8) * 528 + c * 2) = hi2;
                *(__nv_bfloat162*)(sm + SA_LO + (r + 8) * 528 + c * 2) = lo2;
            }
            #pragma unroll
            for (int t = 0; t < 4; ++t) {
                int c = nq * 32 + t * 8 + qc;
                accB[t][0] = sB2[c]; accB[t][1] = sB2[c + 1];
                accB[t][2] = sB2[c]; accB[t][3] = sB2[c + 1];
            }
        }

        if (g + 1 < GT) { CP_WAIT(1); } else { CP_WAIT(0); }
        __syncthreads();

        const int k0 = (ph < 16) ? ph * 16 : (ph - 16) * 16;
        const uint32_t slot = base + W_ST + (uint32_t)(g & 1) * 16896u;

        unsigned ah[4], al[4];
        ldsm4(ah, aH0 + (uint32_t)(k0 + lcol8) * 2);
        ldsm4(al, aL0 + (uint32_t)(k0 + lcol8) * 2);

        if (ph < 16) {
            uint32_t brow = slot + (uint32_t)lrow * 528;
            #pragma unroll
            for (int p = 0; p < 4; ++p) {
                int nb = nq * 64 + p * 16;
                unsigned bh[4], bl[4];
                ldsm4t(bh, brow + (uint32_t)(nb + lcol8) * 2);
                ldsm4t(bl, brow + 8448 + (uint32_t)(nb + lcol8) * 2);
                mma_bf16(accA[2 * p],     ah, bh);
                mma_bf16(accA[2 * p + 1], ah, bh + 2);
                mma_bf16(accA[2 * p],     al, bh);
                mma_bf16(accA[2 * p + 1], al, bh + 2);
                mma_bf16(accA[2 * p],     ah, bl);
                mma_bf16(accA[2 * p + 1], ah, bl + 2);
            }
        } else {
            uint32_t brow = slot + (uint32_t)lrow * 272;
            #pragma unroll
            for (int p = 0; p < 2; ++p) {
                int nb = nq * 32 + p * 16;
                unsigned bh[4], bl[4];
                ldsm4t(bh, brow + (uint32_t)(nb + lcol8) * 2);
                ldsm4t(bl, brow + 4352 + (uint32_t)(nb + lcol8) * 2);
                mma_bf16(accB[2 * p],     ah, bh);
                mma_bf16(accB[2 * p + 1], ah, bh + 2);
                mma_bf16(accB[2 * p],     al, bh);
                mma_bf16(accB[2 * p + 1], al, bh + 2);
                mma_bf16(accB[2 * p],     ah, bl);
                mma_bf16(accB[2 * p + 1], ah, bl + 2);
            }
        }
        __syncthreads();
        if (g + 2 < GT) load_slab<false>((g + 2) & 31, base, tid);
    }

    // level 0 (root): n == 1
    #pragma unroll
    for (int t = 0; t < 4; ++t) {
        int c = nq * 32 + t * 8 + qc;
        #pragma unroll
        for (int h = 0; h < 2; ++h) {
            int r = wr + qr + h * 8;
            if (r < 1)
                *reinterpret_cast<float2*>(out + (size_t)r * 128 + c) =
                    make_float2(lrelu(accB[t][2 * h]), lrelu(accB[t][2 * h + 1]));
        }
    }
}

extern "C" void kernel_launch(void* const* d_in, const int* in_sizes, int n_in,
                              void* d_out, int out_size)
{
    const float* leaf = (const float*)d_in[0];
    const float* We   = (const float*)d_in[1];
    const float* be   = (const float*)d_in[2];
    const float* W1   = (const float*)d_in[3];
    const float* b1   = (const float*)d_in[4];
    const float* W2   = (const float*)d_in[5];
    const float* b2   = (const float*)d_in[6];
    float* out = (float*)d_out;

    cudaFuncSetAttribute(level_kernel<true>,  cudaFuncAttributeMaxDynamicSharedMemorySize, SMEM_LVL);
    cudaFuncSetAttribute(level_kernel<false>, cudaFuncAttributeMaxDynamicSharedMemorySize, SMEM_LVL);
    cudaFuncSetAttribute(tail_kernel,         cudaFuncAttributeMaxDynamicSharedMemorySize, SMEM_LVL);

    prep_kernel<<<256, 256>>>(W1, W2, We);

    const size_t leaf_start = (size_t)(1u << DEPTH) - 1;
    float* Yemb = out + leaf_start * 128;

    for (int l = DEPTH - 1; l >= 7; --l) {
        const int n = 1 << l;
        const size_t p0 = (size_t)(1u << l) - 1;
        float* Y = out + p0 * 128;
        const int grid = (n + 63) / 64;
        if (l == DEPTH - 1) {
            level_kernel<true><<<grid, THREADS, SMEM_LVL>>>(leaf, Y, Yemb, b1, b2, be, n);
        } else {
            const float* X = out + (2 * p0 + 1) * 128;
            level_kernel<false><<<grid, THREADS, SMEM_LVL>>>(X, Y, Yemb, b1, b2, be, n);
        }
    }
    tail_kernel<<<1, THREADS, SMEM_LVL>>>(out, b1, b2);
}

// round 11
// speedup vs baseline: 1.2257x; 1.2257x over previous
#include <cuda_runtime.h>
#include <cuda_bf16.h>
#include <cstdint>

// R11: R8 compute (mma.sync bf16 split-2, 32x64 warp tiles) restructured:
// BM=128 / 512 threads / 1 CTA/SM (16 warps: 4 row-groups x 4 col-quarters),
// 4-slot weight ring -> ONE __syncthreads per stage, cp.async prefetch depth 2.
// Fused leaf embedder (blockdiag(We,We)); ring-4 single-CTA tail for levels 6..0.

static __forceinline__ __device__ float lrelu(float v) { return v > 0.0f ? v : 0.01f * v; }

constexpr int DEPTH = 18;

// level kernel smem map (bytes)
constexpr int L_SA_HI = 0;                  // [128][528B] bf16 hi
constexpr int L_SA_LO = 67584;
constexpr int L_W     = 135168;             // 4 slots x 16896
constexpr int L_SB1   = 202752;             // 1024
constexpr int L_SB2   = 203776;             // 512
constexpr int L_SBE   = 204288;             // 512
constexpr int SMEM_LVL = 204800;

// tail kernel smem map
constexpr int T_SA_HI = 0;                  // [64][528B]
constexpr int T_SA_LO = 33792;
constexpr int T_W     = 67584;              // 4 slots x 16896
constexpr int T_SB1   = 135168;
constexpr int T_SB2   = 136192;
constexpr int SMEM_TAIL = 136704;

// prepped split weights (row-major bf16)
__device__ __align__(16) __nv_bfloat16 W1hi_d[65536];   // [256][256]
__device__ __align__(16) __nv_bfloat16 W1lo_d[65536];
__device__ __align__(16) __nv_bfloat16 W2hi_d[32768];   // [256][128]
__device__ __align__(16) __nv_bfloat16 W2lo_d[32768];
__device__ __align__(16) __nv_bfloat16 WBhi_d[16384];   // blockdiag(We,We) [64][256]
__device__ __align__(16) __nv_bfloat16 WBlo_d[16384];

static __forceinline__ __device__ uint32_t smem_u32(const void* p) {
    uint32_t a;
    asm("{ .reg .u64 t; cvta.to.shared.u64 t, %1; cvt.u32.u64 %0, t; }" : "=r"(a) : "l"(p));
    return a;
}
static __forceinline__ __device__ void cp16(uint32_t d, const void* s) {
    asm volatile("cp.async.cg.shared.global [%0], [%1], 16;" :: "r"(d), "l"(s));
}
#define CP_COMMIT() asm volatile("cp.async.commit_group;" ::: "memory")
#define CP_WAIT(N)  asm volatile("cp.async.wait_group %0;" :: "n"(N) : "memory")

static __forceinline__ __device__ void ldsm4(unsigned* r, uint32_t a) {
    asm volatile("ldmatrix.sync.aligned.m8n8.x4.shared.b16 {%0,%1,%2,%3}, [%4];"
                 : "=r"(r[0]), "=r"(r[1]), "=r"(r[2]), "=r"(r[3]) : "r"(a));
}
static __forceinline__ __device__ void ldsm4t(unsigned* r, uint32_t a) {
    asm volatile("ldmatrix.sync.aligned.m8n8.x4.trans.shared.b16 {%0,%1,%2,%3}, [%4];"
                 : "=r"(r[0]), "=r"(r[1]), "=r"(r[2]), "=r"(r[3]) : "r"(a));
}
static __forceinline__ __device__ void mma_bf16(float* c, const unsigned* a, const unsigned* b) {
    asm volatile("mma.sync.aligned.m16n8k16.row.col.f32.bf16.bf16.f32 "
                 "{%0,%1,%2,%3}, {%4,%5,%6,%7}, {%8,%9}, {%0,%1,%2,%3};"
                 : "+f"(c[0]), "+f"(c[1]), "+f"(c[2]), "+f"(c[3])
                 : "r"(a[0]), "r"(a[1]), "r"(a[2]), "r"(a[3]), "r"(b[0]), "r"(b[1]));
}
static __forceinline__ __device__ void split2(float h0, float h1,
                                              __nv_bfloat162& hi, __nv_bfloat162& lo) {
    hi = __floats2bfloat162_rn(h0, h1);
    lo = __floats2bfloat162_rn(h0 - __bfloat162float(hi.x), h1 - __bfloat162float(hi.y));
}

__global__ void prep_kernel(const float* __restrict__ W1, const float* __restrict__ W2,
                            const float* __restrict__ We) {
    int t = blockIdx.x * 256 + threadIdx.x;
    if (t < 65536) {
        float f = W1[t];
        __nv_bfloat16 hi = __float2bfloat16(f);
        W1hi_d[t] = hi; W1lo_d[t] = __float2bfloat16(f - __bfloat162float(hi));
    }
    if (t < 32768) {
        float f = W2[t];
        __nv_bfloat16 hi = __float2bfloat16(f);
        W2hi_d[t] = hi; W2lo_d[t] = __float2bfloat16(f - __bfloat162float(hi));
    }
    if (t < 16384) {                       // WB[k][c], k<64, c<256
        int k = t >> 8, c = t & 255;
        float f = 0.0f;
        if (k < 32 && c < 128)   f = We[k * 128 + c];
        if (k >= 32 && c >= 128) f = We[(k - 32) * 128 + (c - 128)];
        __nv_bfloat16 hi = __float2bfloat16(f);
        WBhi_d[t] = hi; WBlo_d[t] = __float2bfloat16(f - __bfloat162float(hi));
    }
}

// slab g into ring slot (g&3). All NTHR threads copy equal shares.
template<bool LEAF, int NTHR>
static __forceinline__ __device__ void load_slab(int g, uint32_t wbase, int tid) {
    uint32_t slot = wbase + (uint32_t)(g & 3) * 16896u;
    const char *hi, *lo;
    bool k256;
    if (LEAF) {
        if (g < 4)       { hi = (const char*)WBhi_d + (size_t)g * 8192;        lo = (const char*)WBlo_d + (size_t)g * 8192;        k256 = true; }
        else if (g < 20) { hi = (const char*)W1hi_d + (size_t)(g - 4) * 8192;  lo = (const char*)W1lo_d + (size_t)(g - 4) * 8192;  k256 = true; }
        else             { hi = (const char*)W2hi_d + (size_t)(g - 20) * 4096; lo = (const char*)W2lo_d + (size_t)(g - 20) * 4096; k256 = false; }
    } else {
        if (g < 16)      { hi = (const char*)W1hi_d + (size_t)g * 8192;        lo = (const char*)W1lo_d + (size_t)g * 8192;        k256 = true; }
        else             { hi = (const char*)W2hi_d + (size_t)(g - 16) * 4096; lo = (const char*)W2lo_d + (size_t)(g - 16) * 4096; k256 = false; }
    }
    if (k256) {
        #pragma unroll
        for (int j = 0; j < 1024 / NTHR; ++j) {      // 1024 chunks of 16B
            int idx = tid + j * NTHR;
            int part = idx >> 9, rc = idx & 511, r = rc >> 5, c = rc & 31;
            cp16(slot + part * 8448 + r * 528 + c * 16, (part ? lo : hi) + r * 512 + c * 16);
        }
    } else {
        #pragma unroll
        for (int j = 0; j < 512 / NTHR; ++j) {       // 512 chunks
            int idx = tid + j * NTHR;
            int part = idx >> 8, rc = idx & 255, r = rc >> 4, c = rc & 15;
            cp16(slot + part * 4352 + r * 272 + c * 16, (part ? lo : hi) + r * 256 + c * 16);
        }
    }
    CP_COMMIT();
}

// drain so that slab g is complete (given slabs up to min(G-1, g+2) committed)
template<int G>
static __forceinline__ __device__ void wait_slab(int g) {
    if (g + 3 <= G)      { CP_WAIT(2); }
    else if (g + 2 == G) { CP_WAIT(1); }
    else                 { CP_WAIT(0); }
}

template<bool LEAF>
__global__ void __launch_bounds__(512, 1)
level_kernel(const float* __restrict__ X, float* __restrict__ Y,
             float* __restrict__ Yemb,
             const float* __restrict__ b1, const float* __restrict__ b2,
             const float* __restrict__ be, int n)
{
    extern __shared__ __align__(16) char sm[];
    const uint32_t base = smem_u32(sm);
    const int tid = threadIdx.x, wid = tid >> 5, lane = tid & 31;
    const int rg = wid >> 2, nq = wid & 3;          // 4 row-groups x 4 col-quarters
    const int wr = rg * 32;
    const int row0 = blockIdx.x * 128;
    const int lrow = lane & 15, lcol8 = (lane >> 4) * 8;
    const int qr = lane >> 2, qc = (lane & 3) * 2;

    constexpr int G = LEAF ? 36 : 32;
    constexpr int EPI1_AT = LEAF ? 20 : 16;
    const uint32_t wbase = base + L_W;

    load_slab<LEAF, 512>(0, wbase, tid);
    load_slab<LEAF, 512>(1, wbase, tid);
    load_slab<LEAF, 512>(2, wbase, tid);

    if (tid < 256) ((float*)(sm + L_SB1))[tid] = b1[tid];
    if (tid >= 256 && tid < 384) ((float*)(sm + L_SB2))[tid - 256] = b2[tid - 256];
    if (tid >= 384) ((float*)(sm + L_SBE))[tid - 384] = be[tid - 384];

    // A tile load + split. LEAF: A' [128][64] (2 leaves/row); else X [128][256].
    if (LEAF) {
        const float* Xb = X + (size_t)row0 * 64;
        for (int idx = tid; idx < 128 * 16; idx += 512) {
            int r = idx >> 4, c4 = idx & 15;
            float4 v = make_float4(0.f, 0.f, 0.f, 0.f);
            if (row0 + r < n) v = reinterpret_cast<const float4*>(Xb)[r * 16 + c4];
            __nv_bfloat162 h0, l0, h1, l1;
            split2(v.x, v.y, h0, l0); split2(v.z, v.w, h1, l1);
            uint32_t off = (uint32_t)r * 528 + c4 * 8;
            *(__nv_bfloat162*)(sm + L_SA_HI + off)     = h0;
            *(__nv_bfloat162*)(sm + L_SA_HI + off + 4) = h1;
            *(__nv_bfloat162*)(sm + L_SA_LO + off)     = l0;
            *(__nv_bfloat162*)(sm + L_SA_LO + off + 4) = l1;
        }
    } else {
        for (int idx = tid; idx < 128 * 64; idx += 512) {
            int r = idx >> 6, c4 = idx & 63;
            float4 v = make_float4(0.f, 0.f, 0.f, 0.f);
            if (row0 + r < n) v = reinterpret_cast<const float4*>(X)[(size_t)(row0 + r) * 64 + c4];
            __nv_bfloat162 h0, l0, h1, l1;
            split2(v.x, v.y, h0, l0); split2(v.z, v.w, h1, l1);
            uint32_t off = (uint32_t)r * 528 + c4 * 8;
            *(__nv_bfloat162*)(sm + L_SA_HI + off)     = h0;
            *(__nv_bfloat162*)(sm + L_SA_HI + off + 4) = h1;
            *(__nv_bfloat162*)(sm + L_SA_LO + off)     = l0;
            *(__nv_bfloat162*)(sm + L_SA_LO + off + 4) = l1;
        }
    }
    __syncthreads();                                // publish A tile + biases

    const float* sB1 = (const float*)(sm + L_SB1);
    const float* sB2 = (const float*)(sm + L_SB2);
    const float* sBE = (const float*)(sm + L_SBE);

    float accA[2][8][4];   // emb(leaf)/layer1: warp 32 x 64 (cols nq*64..)
    float accB[2][4][4];   // layer2: warp 32 x 32 (cols nq*32..)
    #pragma unroll
    for (int m = 0; m < 2; ++m)
        #pragma unroll
        for (int t = 0; t < 8; ++t) {
            int c = nq * 64 + t * 8 + qc;
            float v0 = LEAF ? sBE[c & 127] : sB1[c];
            float v1 = LEAF ? sBE[(c + 1) & 127] : sB1[c + 1];
            accA[m][t][0] = v0; accA[m][t][1] = v1; accA[m][t][2] = v0; accA[m][t][3] = v1;
        }

    const uint32_t aH0 = base + L_SA_HI + (uint32_t)(wr + lrow) * 528;
    const uint32_t aH1 = aH0 + 16 * 528;
    const uint32_t aL0 = base + L_SA_LO + (uint32_t)(wr + lrow) * 528;
    const uint32_t aL1 = aL0 + 16 * 528;

    for (int g = 0; g < G; ++g) {
        // cross-warp epilogues (write sA) bracketed by full syncs
        if (LEAF && g == 4) {
            __syncthreads();
            #pragma unroll
            for (int m = 0; m < 2; ++m)
                #pragma unroll
                for (int t = 0; t < 8; ++t) {
                    int c = nq * 64 + t * 8 + qc;
                    int r = wr + m * 16 + qr;
                    float v0 = lrelu(accA[m][t][0]), v1 = lrelu(accA[m][t][1]);
                    float v2 = lrelu(accA[m][t][2]), v3 = lrelu(accA[m][t][3]);
                    __nv_bfloat162 hi2, lo2;
                    split2(v0, v1, hi2, lo2);
                    *(__nv_bfloat162*)(sm + L_SA_HI + r * 528 + c * 2) = hi2;
                    *(__nv_bfloat162*)(sm + L_SA_LO + r * 528 + c * 2) = lo2;
                    if (row0 + r < n)
                        *reinterpret_cast<float2*>(Yemb + (size_t)(row0 + r) * 256 + c) = make_float2(v0, v1);
                    split2(v2, v3, hi2, lo2);
                    *(__nv_bfloat162*)(sm + L_SA_HI + (r + 8) * 528 + c * 2) = hi2;
                    *(__nv_bfloat162*)(sm + L_SA_LO + (r + 8) * 528 + c * 2) = lo2;
                    if (row0 + r + 8 < n)
                        *reinterpret_cast<float2*>(Yemb + (size_t)(row0 + r + 8) * 256 + c) = make_float2(v2, v3);
                }
            #pragma unroll
            for (int m = 0; m < 2; ++m)
                #pragma unroll
                for (int t = 0; t < 8; ++t) {
                    int c = nq * 64 + t * 8 + qc;
                    accA[m][t][0] = sB1[c]; accA[m][t][1] = sB1[c + 1];
                    accA[m][t][2] = sB1[c]; accA[m][t][3] = sB1[c + 1];
                }
            __syncthreads();
        }
        if (g == EPI1_AT) {
            __syncthreads();
            #pragma unroll
            for (int m = 0; m < 2; ++m)
                #pragma unroll
                for (int t = 0; t < 8; ++t) {
                    int c = nq * 64 + t * 8 + qc;
                    int r = wr + m * 16 + qr;
                    __nv_bfloat162 hi2, lo2;
                    split2(lrelu(accA[m][t][0]), lrelu(accA[m][t][1]), hi2, lo2);
                    *(__nv_bfloat162*)(sm + L_SA_HI + r * 528 + c * 2) = hi2;
                    *(__nv_bfloat162*)(sm + L_SA_LO + r * 528 + c * 2) = lo2;
                    split2(lrelu(accA[m][t][2]), lrelu(accA[m][t][3]), hi2, lo2);
                    *(__nv_bfloat162*)(sm + L_SA_HI + (r + 8) * 528 + c * 2) = hi2;
                    *(__nv_bfloat162*)(sm + L_SA_LO + (r + 8) * 528 + c * 2) = lo2;
                }
            #pragma unroll
            for (int m = 0; m < 2; ++m)
                #pragma unroll
                for (int t = 0; t < 4; ++t) {
                    int c = nq * 32 + t * 8 + qc;
                    accB[m][t][0] = sB2[c]; accB[m][t][1] = sB2[c + 1];
                    accB[m][t][2] = sB2[c]; accB[m][t][3] = sB2[c + 1];
                }
            __syncthreads();
        }

        wait_slab<G>(g);
        __syncthreads();                 // slab g visible; slot (g-1)&3 free
        if (g + 3 < G) load_slab<LEAF, 512>(g + 3, wbase, tid);

        int k0;
        if (LEAF) k0 = (g < 4) ? g * 16 : (g < 20 ? (g - 4) * 16 : (g - 20) * 16);
        else      k0 = (g < 16) ? g * 16 : (g - 16) * 16;
        const uint32_t slot = wbase + (uint32_t)(g & 3) * 16896u;

        unsigned ah[2][4], al[2][4];
        ldsm4(ah[0], aH0 + (uint32_t)(k0 + lcol8) * 2);
        ldsm4(ah[1], aH1 + (uint32_t)(k0 + lcol8) * 2);
        ldsm4(al[0], aL0 + (uint32_t)(k0 + lcol8) * 2);
        ldsm4(al[1], aL1 + (uint32_t)(k0 + lcol8) * 2);

        if (g < EPI1_AT) {                                  // K256 phase
            uint32_t brow = slot + (uint32_t)lrow * 528;
            #pragma unroll
            for (int p = 0; p < 4; ++p) {
                int nb = nq * 64 + p * 16;
                unsigned bh[4], bl[4];
                ldsm4t(bh, brow + (uint32_t)(nb + lcol8) * 2);
                ldsm4t(bl, brow + 8448 + (uint32_t)(nb + lcol8) * 2);
                #pragma unroll
                for (int m = 0; m < 2; ++m) {
                    mma_bf16(accA[m][2 * p],     ah[m], bh);
                    mma_bf16(accA[m][2 * p + 1], ah[m], bh + 2);
                    mma_bf16(accA[m][2 * p],     al[m], bh);
                    mma_bf16(accA[m][2 * p + 1], al[m], bh + 2);
                    mma_bf16(accA[m][2 * p],     ah[m], bl);
                    mma_bf16(accA[m][2 * p + 1], ah[m], bl + 2);
                }
            }
        } else {                                            // K128 phase (layer 2)
            uint32_t brow = slot + (uint32_t)lrow * 272;
            #pragma unroll
            for (int p = 0; p < 2; ++p) {
                int nb = nq * 32 + p * 16;
                unsigned bh[4], bl[4];
                ldsm4t(bh, brow + (uint32_t)(nb + lcol8) * 2);
                ldsm4t(bl, brow + 4352 + (uint32_t)(nb + lcol8) * 2);
                #pragma unroll
                for (int m = 0; m < 2; ++m) {
                    mma_bf16(accB[m][2 * p],     ah[m], bh);
                    mma_bf16(accB[m][2 * p + 1], ah[m], bh + 2);
                    mma_bf16(accB[m][2 * p],     al[m], bh);
                    mma_bf16(accB[m][2 * p + 1], al[m], bh + 2);
                    mma_bf16(accB[m][2 * p],     ah[m], bl);
                    mma_bf16(accB[m][2 * p + 1], ah[m], bl + 2);
                }
            }
        }
    }

    // final epilogue: Y = lrelu(accB)
    #pragma unroll
    for (int m = 0; m < 2; ++m)
        #pragma unroll
        for (int t = 0; t < 4; ++t) {
            int c = nq * 32 + t * 8 + qc;
            int r = row0 + wr + m * 16 + qr;
            if (r < n)
                *reinterpret_cast<float2*>(Y + (size_t)r * 128 + c) =
                    make_float2(lrelu(accB[m][t][0]), lrelu(accB[m][t][1]));
            if (r + 8 < n)
                *reinterpret_cast<float2*>(Y + (size_t)(r + 8) * 128 + c) =
                    make_float2(lrelu(accB[m][t][2]), lrelu(accB[m][t][3]));
        }
}

// Tail: levels 6..0 in one 256-thread CTA, ring-4, one sync per stage.
__global__ void __launch_bounds__(256, 1)
tail_kernel(float* __restrict__ out,
            const float* __restrict__ b1, const float* __restrict__ b2)
{
    extern __shared__ __align__(16) char sm[];
    const uint32_t base = smem_u32(sm);
    const int tid = threadIdx.x, wid = tid >> 5, lane = tid & 31;
    const int rg = wid >> 2, nq = wid & 3;
    const int wr = rg * 32;
    const int lrow = lane & 15, lcol8 = (lane >> 4) * 8;
    const int qr = lane >> 2, qc = (lane & 3) * 2;
    const uint32_t wbase = base + T_W;

    load_slab<false, 256>(0, wbase, tid);
    load_slab<false, 256>(1, wbase, tid);
    load_slab<false, 256>(2, wbase, tid);

    ((float*)(sm + T_SB1))[tid] = b1[tid];
    if (tid < 128) ((float*)(sm + T_SB2))[tid] = b2[tid];

    {   // initial A = children of level-6 parents: nodes 127..254 -> [64][256]
        const float* X = out + 127 * 128;
        for (int idx = tid; idx < 64 * 64; idx += 256) {
            int r = idx >> 6, c4 = idx & 63;
            float4 v = reinterpret_cast<const float4*>(X)[r * 64 + c4];
            __nv_bfloat162 h0, l0, h1, l1;
            split2(v.x, v.y, h0, l0); split2(v.z, v.w, h1, l1);
            uint32_t off = (uint32_t)r * 528 + c4 * 8;
            *(__nv_bfloat162*)(sm + T_SA_HI + off)     = h0;
            *(__nv_bfloat162*)(sm + T_SA_HI + off + 4) = h1;
            *(__nv_bfloat162*)(sm + T_SA_LO + off)     = l0;
            *(__nv_bfloat162*)(sm + T_SA_LO + off + 4) = l1;
        }
    }
    __syncthreads();

    const float* sB1 = (const float*)(sm + T_SB1);
    const float* sB2 = (const float*)(sm + T_SB2);

    float accA[2][8][4], accB[2][4][4];
    #pragma unroll
    for (int m = 0; m < 2; ++m)
        #pragma unroll
        for (int t = 0; t < 8; ++t) {
            int c = nq * 64 + t * 8 + qc;
            accA[m][t][0] = sB1[c]; accA[m][t][1] = sB1[c + 1];
            accA[m][t][2] = sB1[c]; accA[m][t][3] = sB1[c + 1];
        }

    const uint32_t aH0 = base + T_SA_HI + (uint32_t)(wr + lrow) * 528;
    const uint32_t aH1 = aH0 + 16 * 528;
    const uint32_t aL0 = base + T_SA_LO + (uint32_t)(wr + lrow) * 528;
    const uint32_t aL1 = aL0 + 16 * 528;

    int n = 64;
    constexpr int GT = 7 * 32;
    for (int g = 0; g < GT; ++g) {
        const int ph = g & 31;
        if (ph == 0 && g > 0) {
            __syncthreads();
            const int lvDone = 7 - (g >> 5);
            float* Y = out + (((size_t)1 << lvDone) - 1) * 128;
            #pragma unroll
            for (int m = 0; m < 2; ++m)
                #pragma unroll
                for (int t = 0; t < 4; ++t) {
                    int c = nq * 32 + t * 8 + qc;
                    #pragma unroll
                    for (int h = 0; h < 2; ++h) {
                        int r = wr + m * 16 + qr + h * 8;
                        float v0 = lrelu(accB[m][t][2 * h]);
                        float v1 = lrelu(accB[m][t][2 * h + 1]);
                        if (r < n)
                            *reinterpret_cast<float2*>(Y + (size_t)r * 128 + c) = make_float2(v0, v1);
                        __nv_bfloat162 hi2, lo2;
                        split2(v0, v1, hi2, lo2);
                        uint32_t off = (uint32_t)(r >> 1) * 528 + ((r & 1) * 128 + c) * 2;
                        *(__nv_bfloat162*)(sm + T_SA_HI + off) = hi2;
                        *(__nv_bfloat162*)(sm + T_SA_LO + off) = lo2;
                    }
                }
            #pragma unroll
            for (int m = 0; m < 2; ++m)
                #pragma unroll
                for (int t = 0; t < 8; ++t) {
                    int c = nq * 64 + t * 8 + qc;
                    accA[m][t][0] = sB1[c]; accA[m][t][1] = sB1[c + 1];
                    accA[m][t][2] = sB1[c]; accA[m][t][3] = sB1[c + 1];
                }
            n >>= 1;
            __syncthreads();
        }
        if (ph == 16) {
            __syncthreads();
            #pragma unroll
            for (int m = 0; m < 2; ++m)
                #pragma unroll
                for (int t = 0; t < 8; ++t) {
                    int c = nq * 64 + t * 8 + qc;
                    int r = wr + m * 16 + qr;
                    __nv_bfloat162 hi2, lo2;
                    split2(lrelu(accA[m][t][0]), lrelu(accA[m][t][1]), hi2, lo2);
                    *(__nv_bfloat162*)(sm + T_SA_HI + r * 528 + c * 2) = hi2;
                    *(__nv_bfloat162*)(sm + T_SA_LO + r * 528 + c * 2) = lo2;
                    split2(lrelu(accA[m][t][2]), lrelu(accA[m][t][3]), hi2, lo2);
                    *(__nv_bfloat162*)(sm + T_SA_HI + (r + 8) * 528 + c * 2) = hi2;
                    *(__nv_bfloat162*)(sm + T_SA_LO + (r + 8) * 528 + c * 2) = lo2;
                }
            #pragma unroll
            for (int m = 0; m < 2; ++m)
                #pragma unroll
                for (int t = 0; t < 4; ++t) {
                    int c = nq * 32 + t * 8 + qc;
                    accB[m][t][0] = sB2[c]; accB[m][t][1] = sB2[c + 1];
                    accB[m][t][2] = sB2[c]; accB[m][t][3] = sB2[c + 1];
                }
            __syncthreads();
        }

        wait_slab<GT>(g);
        __syncthreads();
        if (g + 3 < GT) load_slab<false, 256>((g + 3) & 31, wbase, tid);

        const int k0 = (ph < 16) ? ph * 16 : (ph - 16) * 16;
        const uint32_t slot = wbase + (uint32_t)(g & 3) * 16896u;

        unsigned ah[2][4], al[2][4];
        ldsm4(ah[0], aH0 + (uint32_t)(k0 + lcol8) * 2);
        ldsm4(ah[1], aH1 + (uint32_t)(k0 + lcol8) * 2);
        ldsm4(al[0], aL0 + (uint32_t)(k0 + lcol8) * 2);
        ldsm4(al[1], aL1 + (uint32_t)(k0 + lcol8) * 2);

        if (ph < 16) {
            uint32_t brow = slot + (uint32_t)lrow * 528;
            #pragma unroll
            for (int p = 0; p < 4; ++p) {
                int nb = nq * 64 + p * 16;
                unsigned bh[4], bl[4];
                ldsm4t(bh, brow + (uint32_t)(nb + lcol8) * 2);
                ldsm4t(bl, brow + 8448 + (uint32_t)(nb + lcol8) * 2);
                #pragma unroll
                for (int m = 0; m < 2; ++m) {
                    mma_bf16(accA[m][2 * p],     ah[m], bh);
                    mma_bf16(accA[m][2 * p + 1], ah[m], bh + 2);
                    mma_bf16(accA[m][2 * p],     al[m], bh);
                    mma_bf16(accA[m][2 * p + 1], al[m], bh + 2);
                    mma_bf16(accA[m][2 * p],     ah[m], bl);
                    mma_bf16(accA[m][2 * p + 1], ah[m], bl + 2);
                }
            }
        } else {
            uint32_t brow = slot + (uint32_t)lrow * 272;
            #pragma unroll
            for (int p = 0; p < 2; ++p) {
                int nb = nq * 32 + p * 16;
                unsigned bh[4], bl[4];
                ldsm4t(bh, brow + (uint32_t)(nb + lcol8) * 2);
                ldsm4t(bl, brow + 4352 + (uint32_t)(nb + lcol8) * 2);
                #pragma unroll
                for (int m = 0; m < 2; ++m) {
                    mma_bf16(accB[m][2 * p],     ah[m], bh);
                    mma_bf16(accB[m][2 * p + 1], ah[m], bh + 2);
                    mma_bf16(accB[m][2 * p],     al[m], bh);
                    mma_bf16(accB[m][2 * p + 1], al[m], bh + 2);
                    mma_bf16(accB[m][2 * p],     ah[m], bl);
                    mma_bf16(accB[m][2 * p + 1], ah[m], bl + 2);
                }
            }
        }
    }

    // level 0 (root): n == 1
    #pragma unroll
    for (int m = 0; m < 2; ++m)
        #pragma unroll
        for (int t = 0; t < 4; ++t) {
            int c = nq * 32 + t * 8 + qc;
            #pragma unroll
            for (int h = 0; h < 2; ++h) {
                int r = wr + m * 16 + qr + h * 8;
                if (r < 1)
                    *reinterpret_cast<float2*>(out + (size_t)r * 128 + c) =
                        make_float2(lrelu(accB[m][t][2 * h]), lrelu(accB[m][t][2 * h + 1]));
            }
        }
}

extern "C" void kernel_launch(void* const* d_in, const int* in_sizes, int n_in,
                              void* d_out, int out_size)
{
    const float* leaf = (const float*)d_in[0];
    const float* We   = (const float*)d_in[1];
    const float* be   = (const float*)d_in[2];
    const float* W1   = (const float*)d_in[3];
    const float* b1   = (const float*)d_in[4];
    const float* W2   = (const float*)d_in[5];
    const float* b2   = (const float*)d_in[6];
    float* out = (float*)d_out;

    cudaFuncSetAttribute(level_kernel<true>,  cudaFuncAttributeMaxDynamicSharedMemorySize, SMEM_LVL);
    cudaFuncSetAttribute(level_kernel<false>, cudaFuncAttributeMaxDynamicSharedMemorySize, SMEM_LVL);
    cudaFuncSetAttribute(tail_kernel,         cudaFuncAttributeMaxDynamicSharedMemorySize, SMEM_TAIL);

    prep_kernel<<<256, 256>>>(W1, W2, We);

    const size_t leaf_start = (size_t)(1u << DEPTH) - 1;
    float* Yemb = out + leaf_start * 128;

    for (int l = DEPTH - 1; l >= 7; --l) {
        const int n = 1 << l;
        const size_t p0 = (size_t)(1u << l) - 1;
        float* Y = out + p0 * 128;
        const int grid = (n + 127) / 128;
        if (l == DEPTH - 1) {
            level_kernel<true><<<grid, 512, SMEM_LVL>>>(leaf, Y, Yemb, b1, b2, be, n);
        } else {
            const float* X = out + (2 * p0 + 1) * 128;
            level_kernel<false><<<grid, 512, SMEM_LVL>>>(X, Y, Yemb, b1, b2, be, n);
        }
    }
    tail_kernel<<<1, 256, SMEM_TAIL>>>(out, b1, b2);
}

// round 12
// speedup vs baseline: 1.5826x; 1.2912x over previous
#include <cuda_runtime.h>
#include <cuda_bf16.h>
#include <cstdint>

// R12: R8 (proven) for big levels 17..14; NEW K-slab-64 kernels (8 stages
// per level instead of 32) for latency-bound small levels 13..7 and the
// single-CTA tail (levels 6..0, 56 stages instead of 224).

static __forceinline__ __device__ float lrelu(float v) { return v > 0.0f ? v : 0.01f * v; }

constexpr int DEPTH = 18;
// big-level kernel smem map (R8)
constexpr int SA_HI = 0;        // [64][528B] bf16
constexpr int SA_LO = 33792;
constexpr int W_ST  = 67584;    // 2 slots x 16896
constexpr int SB1   = 101376;
constexpr int SB2   = 102400;
constexpr int SBE   = 102912;
constexpr int SMEM_LVL = 103424;

// slab64 kernels smem map
constexpr int S_W   = 67584;              // 2 slots x 67584
constexpr int S_SB1 = 67584 + 135168;     // 202752
constexpr int S_SB2 = 203776;
constexpr int SMEM_SMALL = 204288;

// prepped split weights (row-major bf16)
__device__ __align__(16) __nv_bfloat16 W1hi_d[65536];   // [256][256]
__device__ __align__(16) __nv_bfloat16 W1lo_d[65536];
__device__ __align__(16) __nv_bfloat16 W2hi_d[32768];   // [256][128]
__device__ __align__(16) __nv_bfloat16 W2lo_d[32768];
__device__ __align__(16) __nv_bfloat16 WBhi_d[16384];   // blockdiag(We,We) [64][256]
__device__ __align__(16) __nv_bfloat16 WBlo_d[16384];

static __forceinline__ __device__ uint32_t smem_u32(const void* p) {
    uint32_t a;
    asm("{ .reg .u64 t; cvta.to.shared.u64 t, %1; cvt.u32.u64 %0, t; }" : "=r"(a) : "l"(p));
    return a;
}
static __forceinline__ __device__ void cp16(uint32_t d, const void* s) {
    asm volatile("cp.async.cg.shared.global [%0], [%1], 16;" :: "r"(d), "l"(s));
}
#define CP_COMMIT() asm volatile("cp.async.commit_group;" ::: "memory")
#define CP_WAIT(N)  asm volatile("cp.async.wait_group %0;" :: "n"(N) : "memory")

static __forceinline__ __device__ void ldsm4(unsigned* r, uint32_t a) {
    asm volatile("ldmatrix.sync.aligned.m8n8.x4.shared.b16 {%0,%1,%2,%3}, [%4];"
                 : "=r"(r[0]), "=r"(r[1]), "=r"(r[2]), "=r"(r[3]) : "r"(a));
}
static __forceinline__ __device__ void ldsm4t(unsigned* r, uint32_t a) {
    asm volatile("ldmatrix.sync.aligned.m8n8.x4.trans.shared.b16 {%0,%1,%2,%3}, [%4];"
                 : "=r"(r[0]), "=r"(r[1]), "=r"(r[2]), "=r"(r[3]) : "r"(a));
}
static __forceinline__ __device__ void mma_bf16(float* c, const unsigned* a, const unsigned* b) {
    asm volatile("mma.sync.aligned.m16n8k16.row.col.f32.bf16.bf16.f32 "
                 "{%0,%1,%2,%3}, {%4,%5,%6,%7}, {%8,%9}, {%0,%1,%2,%3};"
                 : "+f"(c[0]), "+f"(c[1]), "+f"(c[2]), "+f"(c[3])
                 : "r"(a[0]), "r"(a[1]), "r"(a[2]), "r"(a[3]), "r"(b[0]), "r"(b[1]));
}
static __forceinline__ __device__ void split2(float h0, float h1,
                                              __nv_bfloat162& hi, __nv_bfloat162& lo) {
    hi = __floats2bfloat162_rn(h0, h1);
    lo = __floats2bfloat162_rn(h0 - __bfloat162float(hi.x), h1 - __bfloat162float(hi.y));
}

__global__ void prep_kernel(const float* __restrict__ W1, const float* __restrict__ W2,
                            const float* __restrict__ We) {
    int t = blockIdx.x * 256 + threadIdx.x;
    if (t < 65536) {
        float f = W1[t];
        __nv_bfloat16 hi = __float2bfloat16(f);
        W1hi_d[t] = hi; W1lo_d[t] = __float2bfloat16(f - __bfloat162float(hi));
    }
    if (t < 32768) {
        float f = W2[t];
        __nv_bfloat16 hi = __float2bfloat16(f);
        W2hi_d[t] = hi; W2lo_d[t] = __float2bfloat16(f - __bfloat162float(hi));
    }
    if (t < 16384) {                       // WB[k][c], k<64, c<256
        int k = t >> 8, c = t & 255;
        float f = 0.0f;
        if (k < 32 && c < 128)   f = We[k * 128 + c];
        if (k >= 32 && c >= 128) f = We[(k - 32) * 128 + (c - 128)];
        __nv_bfloat16 hi = __float2bfloat16(f);
        WBhi_d[t] = hi; WBlo_d[t] = __float2bfloat16(f - __bfloat162float(hi));
    }
}

// ---------- R8 big-level slab loader (16 k-rows) ----------
template<bool LEAF>
static __forceinline__ __device__ void load_slab(int g, uint32_t base, int tid) {
    uint32_t slot = base + W_ST + (uint32_t)(g & 1) * 16896u;
    const char *hi, *lo;
    bool k256;
    if (LEAF) {
        if (g < 4)       { hi = (const char*)WBhi_d + (size_t)g * 8192;        lo = (const char*)WBlo_d + (size_t)g * 8192;        k256 = true; }
        else if (g < 20) { hi = (const char*)W1hi_d + (size_t)(g - 4) * 8192;  lo = (const char*)W1lo_d + (size_t)(g - 4) * 8192;  k256 = true; }
        else             { hi = (const char*)W2hi_d + (size_t)(g - 20) * 4096; lo = (const char*)W2lo_d + (size_t)(g - 20) * 4096; k256 = false; }
    } else {
        if (g < 16)      { hi = (const char*)W1hi_d + (size_t)g * 8192;        lo = (const char*)W1lo_d + (size_t)g * 8192;        k256 = true; }
        else             { hi = (const char*)W2hi_d + (size_t)(g - 16) * 4096; lo = (const char*)W2lo_d + (size_t)(g - 16) * 4096; k256 = false; }
    }
    if (k256) {
        #pragma unroll
        for (int j = 0; j < 4; ++j) {
            int idx = tid + j * 256;
            int part = idx >> 9, rc = idx & 511, r = rc >> 5, c = rc & 31;
            cp16(slot + part * 8448 + r * 528 + c * 16, (part ? lo : hi) + r * 512 + c * 16);
        }
    } else {
        #pragma unroll
        for (int j = 0; j < 2; ++j) {
            int idx = tid + j * 256;
            int part = idx >> 8, rc = idx & 255, r = rc >> 4, c = rc & 15;
            cp16(slot + part * 4352 + r * 272 + c * 16, (part ? lo : hi) + r * 256 + c * 16);
        }
    }
    CP_COMMIT();
}

// ---------- slab64 loader: g 0..3 -> W1 64-row slabs, 4..7 -> W2 ----------
static __forceinline__ __device__ void load_slab64(int g, uint32_t wbase, int tid) {
    uint32_t slot = wbase + (uint32_t)(g & 1) * 67584u;
    if (g < 4) {
        const char* hi = (const char*)W1hi_d + (size_t)g * 32768;
        const char* lo = (const char*)W1lo_d + (size_t)g * 32768;
        #pragma unroll
        for (int j = 0; j < 16; ++j) {               // 4096 chunks of 16B
            int idx = tid + j * 256;
            int part = idx >> 11, rc = idx & 2047, r = rc >> 5, c = rc & 31;
            cp16(slot + part * 33792 + r * 528 + c * 16, (part ? lo : hi) + r * 512 + c * 16);
        }
    } else {
        const char* hi = (const char*)W2hi_d + (size_t)(g - 4) * 16384;
        const char* lo = (const char*)W2lo_d + (size_t)(g - 4) * 16384;
        #pragma unroll
        for (int j = 0; j < 8; ++j) {                // 2048 chunks
            int idx = tid + j * 256;
            int part = idx >> 10, rc = idx & 1023, r = rc >> 4, c = rc & 15;
            cp16(slot + part * 17408 + r * 272 + c * 16, (part ? lo : hi) + r * 256 + c * 16);
        }
    }
    CP_COMMIT();
}

// ---------- R8 big-level kernel (levels 17..14) ----------
template<bool LEAF>
__global__ void __launch_bounds__(256, 2)
level_kernel(const float* __restrict__ X, float* __restrict__ Y,
             float* __restrict__ Yemb,
             const float* __restrict__ b1, const float* __restrict__ b2,
             const float* __restrict__ be, int n)
{
    extern __shared__ __align__(16) char sm[];
    const uint32_t base = smem_u32(sm);
    const int tid = threadIdx.x, wid = tid >> 5, lane = tid & 31;
    const int rg = wid >> 2, nq = wid & 3;
    const int wr = rg * 32;
    const int row0 = blockIdx.x * 64;
    const int lrow = lane & 15, lcol8 = (lane >> 4) * 8;
    const int qr = lane >> 2, qc = (lane & 3) * 2;

    constexpr int G = LEAF ? 36 : 32;
    constexpr int EPI1_AT = LEAF ? 20 : 16;

    load_slab<LEAF>(0, base, tid);
    load_slab<LEAF>(1, base, tid);

    ((float*)(sm + SB1))[tid] = b1[tid];
    if (tid < 128) ((float*)(sm + SB2))[tid] = b2[tid];
    if (tid < 128) ((float*)(sm + SBE))[tid] = be[tid];

    if (LEAF) {
        const float* Xb = X + (size_t)row0 * 64;
        for (int idx = tid; idx < 64 * 16; idx += 256) {
            int r = idx >> 4, c4 = idx & 15;
            float4 v = make_float4(0.f, 0.f, 0.f, 0.f);
            if (row0 + r < n) v = reinterpret_cast<const float4*>(Xb)[r * 16 + c4];
            __nv_bfloat162 h0, l0, h1, l1;
            split2(v.x, v.y, h0, l0); split2(v.z, v.w, h1, l1);
            uint32_t off = (uint32_t)r * 528 + c4 * 8;
            *(__nv_bfloat162*)(sm + SA_HI + off)     = h0;
            *(__nv_bfloat162*)(sm + SA_HI + off + 4) = h1;
            *(__nv_bfloat162*)(sm + SA_LO + off)     = l0;
            *(__nv_bfloat162*)(sm + SA_LO + off + 4) = l1;
        }
    } else {
        for (int idx = tid; idx < 64 * 64; idx += 256) {
            int r = idx >> 6, c4 = idx & 63;
            float4 v = make_float4(0.f, 0.f, 0.f, 0.f);
            if (row0 + r < n) v = reinterpret_cast<const float4*>(X)[(size_t)(row0 + r) * 64 + c4];
            __nv_bfloat162 h0, l0, h1, l1;
            split2(v.x, v.y, h0, l0); split2(v.z, v.w, h1, l1);
            uint32_t off = (uint32_t)r * 528 + c4 * 8;
            *(__nv_bfloat162*)(sm + SA_HI + off)     = h0;
            *(__nv_bfloat162*)(sm + SA_HI + off + 4) = h1;
            *(__nv_bfloat162*)(sm + SA_LO + off)     = l0;
            *(__nv_bfloat162*)(sm + SA_LO + off + 4) = l1;
        }
    }
    __syncthreads();                 // publish biases + A tile (fixes latent race)

    const float* sB1 = (const float*)(sm + SB1);
    const float* sB2 = (const float*)(sm + SB2);
    const float* sBE = (const float*)(sm + SBE);

    float accA[2][8][4];
    float accB[2][4][4];
    #pragma unroll
    for (int m = 0; m < 2; ++m)
        #pragma unroll
        for (int t = 0; t < 8; ++t) {
            int c = nq * 64 + t * 8 + qc;
            float v0 = LEAF ? sBE[c & 127] : sB1[c];
            float v1 = LEAF ? sBE[(c + 1) & 127] : sB1[c + 1];
            accA[m][t][0] = v0; accA[m][t][1] = v1; accA[m][t][2] = v0; accA[m][t][3] = v1;
        }

    const uint32_t aH0 = base + SA_HI + (uint32_t)(wr + lrow) * 528;
    const uint32_t aH1 = aH0 + 16 * 528;
    const uint32_t aL0 = base + SA_LO + (uint32_t)(wr + lrow) * 528;
    const uint32_t aL1 = aL0 + 16 * 528;

    for (int g = 0; g < G; ++g) {
        if (LEAF && g == 4) {
            #pragma unroll
            for (int m = 0; m < 2; ++m)
                #pragma unroll
                for (int t = 0; t < 8; ++t) {
                    int c = nq * 64 + t * 8 + qc;
                    int r = wr + m * 16 + qr;
                    float v0 = lrelu(accA[m][t][0]), v1 = lrelu(accA[m][t][1]);
                    float v2 = lrelu(accA[m][t][2]), v3 = lrelu(accA[m][t][3]);
                    __nv_bfloat162 hi2, lo2;
                    split2(v0, v1, hi2, lo2);
                    *(__nv_bfloat162*)(sm + SA_HI + r * 528 + c * 2) = hi2;
                    *(__nv_bfloat162*)(sm + SA_LO + r * 528 + c * 2) = lo2;
                    if (row0 + r < n)
                        *reinterpret_cast<float2*>(Yemb + (size_t)(row0 + r) * 256 + c) = make_float2(v0, v1);
                    split2(v2, v3, hi2, lo2);
                    *(__nv_bfloat162*)(sm + SA_HI + (r + 8) * 528 + c * 2) = hi2;
                    *(__nv_bfloat162*)(sm + SA_LO + (r + 8) * 528 + c * 2) = lo2;
                    if (row0 + r + 8 < n)
                        *reinterpret_cast<float2*>(Yemb + (size_t)(row0 + r + 8) * 256 + c) = make_float2(v2, v3);
                }
            #pragma unroll
            for (int m = 0; m < 2; ++m)
                #pragma unroll
                for (int t = 0; t < 8; ++t) {
                    int c = nq * 64 + t * 8 + qc;
                    accA[m][t][0] = sB1[c]; accA[m][t][1] = sB1[c + 1];
                    accA[m][t][2] = sB1[c]; accA[m][t][3] = sB1[c + 1];
                }
        }
        if (g == EPI1_AT) {
            #pragma unroll
            for (int m = 0; m < 2; ++m)
                #pragma unroll
                for (int t = 0; t < 8; ++t) {
                    int c = nq * 64 + t * 8 + qc;
                    int r = wr + m * 16 + qr;
                    __nv_bfloat162 hi2, lo2;
                    split2(lrelu(accA[m][t][0]), lrelu(accA[m][t][1]), hi2, lo2);
                    *(__nv_bfloat162*)(sm + SA_HI + r * 528 + c * 2) = hi2;
                    *(__nv_bfloat162*)(sm + SA_LO + r * 528 + c * 2) = lo2;
                    split2(lrelu(accA[m][t][2]), lrelu(accA[m][t][3]), hi2, lo2);
                    *(__nv_bfloat162*)(sm + SA_HI + (r + 8) * 528 + c * 2) = hi2;
                    *(__nv_bfloat162*)(sm + SA_LO + (r + 8) * 528 + c * 2) = lo2;
                }
            #pragma unroll
            for (int m = 0; m < 2; ++m)
                #pragma unroll
                for (int t = 0; t < 4; ++t) {
                    int c = nq * 32 + t * 8 + qc;
                    accB[m][t][0] = sB2[c]; accB[m][t][1] = sB2[c + 1];
                    accB[m][t][2] = sB2[c]; accB[m][t][3] = sB2[c + 1];
                }
        }

        if (g + 1 < G) { CP_WAIT(1); } else { CP_WAIT(0); }
        __syncthreads();

        int k0;
        if (LEAF) k0 = (g < 4) ? g * 16 : (g < 20 ? (g - 4) * 16 : (g - 20) * 16);
        else      k0 = (g < 16) ? g * 16 : (g - 16) * 16;
        const uint32_t slot = base + W_ST + (uint32_t)(g & 1) * 16896u;

        unsigned ah[2][4], al[2][4];
        ldsm4(ah[0], aH0 + (uint32_t)(k0 + lcol8) * 2);
        ldsm4(ah[1], aH1 + (uint32_t)(k0 + lcol8) * 2);
        ldsm4(al[0], aL0 + (uint32_t)(k0 + lcol8) * 2);
        ldsm4(al[1], aL1 + (uint32_t)(k0 + lcol8) * 2);

        if (g < EPI1_AT) {
            uint32_t brow = slot + (uint32_t)lrow * 528;
            #pragma unroll
            for (int p = 0; p < 4; ++p) {
                int nb = nq * 64 + p * 16;
                unsigned bh[4], bl[4];
                ldsm4t(bh, brow + (uint32_t)(nb + lcol8) * 2);
                ldsm4t(bl, brow + 8448 + (uint32_t)(nb + lcol8) * 2);
                #pragma unroll
                for (int m = 0; m < 2; ++m) {
                    mma_bf16(accA[m][2 * p],     ah[m], bh);
                    mma_bf16(accA[m][2 * p + 1], ah[m], bh + 2);
                    mma_bf16(accA[m][2 * p],     al[m], bh);
                    mma_bf16(accA[m][2 * p + 1], al[m], bh + 2);
                    mma_bf16(accA[m][2 * p],     ah[m], bl);
                    mma_bf16(accA[m][2 * p + 1], ah[m], bl + 2);
                }
            }
        } else {
            uint32_t brow = slot + (uint32_t)lrow * 272;
            #pragma unroll
            for (int p = 0; p < 2; ++p) {
                int nb = nq * 32 + p * 16;
                unsigned bh[4], bl[4];
                ldsm4t(bh, brow + (uint32_t)(nb + lcol8) * 2);
                ldsm4t(bl, brow + 4352 + (uint32_t)(nb + lcol8) * 2);
                #pragma unroll
                for (int m = 0; m < 2; ++m) {
                    mma_bf16(accB[m][2 * p],     ah[m], bh);
                    mma_bf16(accB[m][2 * p + 1], ah[m], bh + 2);
                    mma_bf16(accB[m][2 * p],     al[m], bh);
                    mma_bf16(accB[m][2 * p + 1], al[m], bh + 2);
                    mma_bf16(accB[m][2 * p],     ah[m], bl);
                    mma_bf16(accB[m][2 * p + 1], ah[m], bl + 2);
                }
            }
        }
        __syncthreads();
        if (g + 2 < G) load_slab<LEAF>(g + 2, base, tid);
    }

    #pragma unroll
    for (int m = 0; m < 2; ++m)
        #pragma unroll
        for (int t = 0; t < 4; ++t) {
            int c = nq * 32 + t * 8 + qc;
            int r = row0 + wr + m * 16 + qr;
            if (r < n)
                *reinterpret_cast<float2*>(Y + (size_t)r * 128 + c) =
                    make_float2(lrelu(accB[m][t][0]), lrelu(accB[m][t][1]));
            if (r + 8 < n)
                *reinterpret_cast<float2*>(Y + (size_t)(r + 8) * 128 + c) =
                    make_float2(lrelu(accB[m][t][2]), lrelu(accB[m][t][3]));
        }
}

// ---------- slab64 compute macro-free inner sub-stage ----------
// (shared structure; written inline in both kernels below)

// small levels 13..7: one level per launch, 8 stages, K-slab 64.
__global__ void __launch_bounds__(256, 1)
small_kernel(const float* __restrict__ X, float* __restrict__ Y,
             const float* __restrict__ b1, const float* __restrict__ b2, int n)
{
    extern __shared__ __align__(16) char sm[];
    const uint32_t base = smem_u32(sm);
    const int tid = threadIdx.x, wid = tid >> 5, lane = tid & 31;
    const int rg = wid >> 2, nq = wid & 3;
    const int wr = rg * 32;
    const int row0 = blockIdx.x * 64;
    const int lrow = lane & 15, lcol8 = (lane >> 4) * 8;
    const int qr = lane >> 2, qc = (lane & 3) * 2;
    const uint32_t wbase = base + S_W;

    load_slab64(0, wbase, tid);
    load_slab64(1, wbase, tid);

    ((float*)(sm + S_SB1))[tid] = b1[tid];
    if (tid < 128) ((float*)(sm + S_SB2))[tid] = b2[tid];

    for (int idx = tid; idx < 64 * 64; idx += 256) {
        int r = idx >> 6, c4 = idx & 63;
        float4 v = make_float4(0.f, 0.f, 0.f, 0.f);
        if (row0 + r < n) v = reinterpret_cast<const float4*>(X)[(size_t)(row0 + r) * 64 + c4];
        __nv_bfloat162 h0, l0, h1, l1;
        split2(v.x, v.y, h0, l0); split2(v.z, v.w, h1, l1);
        uint32_t off = (uint32_t)r * 528 + c4 * 8;
        *(__nv_bfloat162*)(sm + SA_HI + off)     = h0;
        *(__nv_bfloat162*)(sm + SA_HI + off + 4) = h1;
        *(__nv_bfloat162*)(sm + SA_LO + off)     = l0;
        *(__nv_bfloat162*)(sm + SA_LO + off + 4) = l1;
    }
    __syncthreads();

    const float* sB1 = (const float*)(sm + S_SB1);
    const float* sB2 = (const float*)(sm + S_SB2);

    float accA[2][8][4], accB[2][4][4];
    #pragma unroll
    for (int m = 0; m < 2; ++m)
        #pragma unroll
        for (int t = 0; t < 8; ++t) {
            int c = nq * 64 + t * 8 + qc;
            accA[m][t][0] = sB1[c]; accA[m][t][1] = sB1[c + 1];
            accA[m][t][2] = sB1[c]; accA[m][t][3] = sB1[c + 1];
        }

    const uint32_t aH0 = base + SA_HI + (uint32_t)(wr + lrow) * 528;
    const uint32_t aH1 = aH0 + 16 * 528;
    const uint32_t aL0 = base + SA_LO + (uint32_t)(wr + lrow) * 528;
    const uint32_t aL1 = aL0 + 16 * 528;

    for (int g = 0; g < 8; ++g) {
        if (g == 4) {   // epilogue 1
            #pragma unroll
            for (int m = 0; m < 2; ++m)
                #pragma unroll
                for (int t = 0; t < 8; ++t) {
                    int c = nq * 64 + t * 8 + qc;
                    int r = wr + m * 16 + qr;
                    __nv_bfloat162 hi2, lo2;
                    split2(lrelu(accA[m][t][0]), lrelu(accA[m][t][1]), hi2, lo2);
                    *(__nv_bfloat162*)(sm + SA_HI + r * 528 + c * 2) = hi2;
                    *(__nv_bfloat162*)(sm + SA_LO + r * 528 + c * 2) = lo2;
                    split2(lrelu(accA[m][t][2]), lrelu(accA[m][t][3]), hi2, lo2);
                    *(__nv_bfloat162*)(sm + SA_HI + (r + 8) * 528 + c * 2) = hi2;
                    *(__nv_bfloat162*)(sm + SA_LO + (r + 8) * 528 + c * 2) = lo2;
                }
            #pragma unroll
            for (int m = 0; m < 2; ++m)
                #pragma unroll
                for (int t = 0; t < 4; ++t) {
                    int c = nq * 32 + t * 8 + qc;
                    accB[m][t][0] = sB2[c]; accB[m][t][1] = sB2[c + 1];
                    accB[m][t][2] = sB2[c]; accB[m][t][3] = sB2[c + 1];
                }
        }

        if (g + 1 < 8) { CP_WAIT(1); } else { CP_WAIT(0); }
        __syncthreads();

        const uint32_t slot = wbase + (uint32_t)(g & 1) * 67584u;
        const int kb = (g < 4 ? g : g - 4) * 64;

        #pragma unroll
        for (int j = 0; j < 4; ++j) {
            const int k0 = kb + j * 16;
            unsigned ah[2][4], al[2][4];
            ldsm4(ah[0], aH0 + (uint32_t)(k0 + lcol8) * 2);
            ldsm4(ah[1], aH1 + (uint32_t)(k0 + lcol8) * 2);
            ldsm4(al[0], aL0 + (uint32_t)(k0 + lcol8) * 2);
            ldsm4(al[1], aL1 + (uint32_t)(k0 + lcol8) * 2);
            if (g < 4) {
                uint32_t brow = slot + (uint32_t)(j * 16 + lrow) * 528;
                #pragma unroll
                for (int p = 0; p < 4; ++p) {
                    int nb = nq * 64 + p * 16;
                    unsigned bh[4], bl[4];
                    ldsm4t(bh, brow + (uint32_t)(nb + lcol8) * 2);
                    ldsm4t(bl, brow + 33792 + (uint32_t)(nb + lcol8) * 2);
                    #pragma unroll
                    for (int m = 0; m < 2; ++m) {
                        mma_bf16(accA[m][2 * p],     ah[m], bh);
                        mma_bf16(accA[m][2 * p + 1], ah[m], bh + 2);
                        mma_bf16(accA[m][2 * p],     al[m], bh);
                        mma_bf16(accA[m][2 * p + 1], al[m], bh + 2);
                        mma_bf16(accA[m][2 * p],     ah[m], bl);
                        mma_bf16(accA[m][2 * p + 1], ah[m], bl + 2);
                    }
                }
            } else {
                uint32_t brow = slot + (uint32_t)(j * 16 + lrow) * 272;
                #pragma unroll
                for (int p = 0; p < 2; ++p) {
                    int nb = nq * 32 + p * 16;
                    unsigned bh[4], bl[4];
                    ldsm4t(bh, brow + (uint32_t)(nb + lcol8) * 2);
                    ldsm4t(bl, brow + 17408 + (uint32_t)(nb + lcol8) * 2);
                    #pragma unroll
                    for (int m = 0; m < 2; ++m) {
                        mma_bf16(accB[m][2 * p],     ah[m], bh);
                        mma_bf16(accB[m][2 * p + 1], ah[m], bh + 2);
                        mma_bf16(accB[m][2 * p],     al[m], bh);
                        mma_bf16(accB[m][2 * p + 1], al[m], bh + 2);
                        mma_bf16(accB[m][2 * p],     ah[m], bl);
                        mma_bf16(accB[m][2 * p + 1], ah[m], bl + 2);
                    }
                }
            }
        }
        __syncthreads();
        if (g + 2 < 8) load_slab64(g + 2, wbase, tid);
    }

    #pragma unroll
    for (int m = 0; m < 2; ++m)
        #pragma unroll
        for (int t = 0; t < 4; ++t) {
            int c = nq * 32 + t * 8 + qc;
            int r = row0 + wr + m * 16 + qr;
            if (r < n)
                *reinterpret_cast<float2*>(Y + (size_t)r * 128 + c) =
                    make_float2(lrelu(accB[m][t][0]), lrelu(accB[m][t][1]));
            if (r + 8 < n)
                *reinterpret_cast<float2*>(Y + (size_t)(r + 8) * 128 + c) =
                    make_float2(lrelu(accB[m][t][2]), lrelu(accB[m][t][3]));
        }
}

// tail: levels 6..0 in one CTA, 7 x 8 = 56 stages, K-slab 64.
__global__ void __launch_bounds__(256, 1)
tail_kernel(float* __restrict__ out,
            const float* __restrict__ b1, const float* __restrict__ b2)
{
    extern __shared__ __align__(16) char sm[];
    const uint32_t base = smem_u32(sm);
    const int tid = threadIdx.x, wid = tid >> 5, lane = tid & 31;
    const int rg = wid >> 2, nq = wid & 3;
    const int wr = rg * 32;
    const int lrow = lane & 15, lcol8 = (lane >> 4) * 8;
    const int qr = lane >> 2, qc = (lane & 3) * 2;
    const uint32_t wbase = base + S_W;

    load_slab64(0, wbase, tid);
    load_slab64(1, wbase, tid);

    ((float*)(sm + S_SB1))[tid] = b1[tid];
    if (tid < 128) ((float*)(sm + S_SB2))[tid] = b2[tid];

    {   // initial A = children of level-6 parents: nodes 127..254
        const float* X = out + 127 * 128;
        for (int idx = tid; idx < 64 * 64; idx += 256) {
            int r = idx >> 6, c4 = idx & 63;
            float4 v = reinterpret_cast<const float4*>(X)[r * 64 + c4];
            __nv_bfloat162 h0, l0, h1, l1;
            split2(v.x, v.y, h0, l0); split2(v.z, v.w, h1, l1);
            uint32_t off = (uint32_t)r * 528 + c4 * 8;
            *(__nv_bfloat162*)(sm + SA_HI + off)     = h0;
            *(__nv_bfloat162*)(sm + SA_HI + off + 4) = h1;
            *(__nv_bfloat162*)(sm + SA_LO + off)     = l0;
            *(__nv_bfloat162*)(sm + SA_LO + off + 4) = l1;
        }
    }
    __syncthreads();

    const float* sB1 = (const float*)(sm + S_SB1);
    const float* sB2 = (const float*)(sm + S_SB2);

    float accA[2][8][4], accB[2][4][4];
    #pragma unroll
    for (int m = 0; m < 2; ++m)
        #pragma unroll
        for (int t = 0; t < 8; ++t) {
            int c = nq * 64 + t * 8 + qc;
            accA[m][t][0] = sB1[c]; accA[m][t][1] = sB1[c + 1];
            accA[m][t][2] = sB1[c]; accA[m][t][3] = sB1[c + 1];
        }

    const uint32_t aH0 = base + SA_HI + (uint32_t)(wr + lrow) * 528;
    const uint32_t aH1 = aH0 + 16 * 528;
    const uint32_t aL0 = base + SA_LO + (uint32_t)(wr + lrow) * 528;
    const uint32_t aL1 = aL0 + 16 * 528;

    int n = 64;
    constexpr int GT = 7 * 8;
    for (int g = 0; g < GT; ++g) {
        const int ph = g & 7;
        if (ph == 0 && g > 0) {    // level done: store Y, repack next A, reset accA
            const int lvDone = 7 - (g >> 3);
            float* Y = out + (((size_t)1 << lvDone) - 1) * 128;
            #pragma unroll
            for (int m = 0; m < 2; ++m)
                #pragma unroll
                for (int t = 0; t < 4; ++t) {
                    int c = nq * 32 + t * 8 + qc;
                    #pragma unroll
                    for (int h = 0; h < 2; ++h) {
                        int r = wr + m * 16 + qr + h * 8;
                        float v0 = lrelu(accB[m][t][2 * h]);
                        float v1 = lrelu(accB[m][t][2 * h + 1]);
                        if (r < n)
                            *reinterpret_cast<float2*>(Y + (size_t)r * 128 + c) = make_float2(v0, v1);
                        __nv_bfloat162 hi2, lo2;
                        split2(v0, v1, hi2, lo2);
                        uint32_t off = (uint32_t)(r >> 1) * 528 + ((r & 1) * 128 + c) * 2;
                        *(__nv_bfloat162*)(sm + SA_HI + off) = hi2;
                        *(__nv_bfloat162*)(sm + SA_LO + off) = lo2;
                    }
                }
            #pragma unroll
            for (int m = 0; m < 2; ++m)
                #pragma unroll
                for (int t = 0; t < 8; ++t) {
                    int c = nq * 64 + t * 8 + qc;
                    accA[m][t][0] = sB1[c]; accA[m][t][1] = sB1[c + 1];
                    accA[m][t][2] = sB1[c]; accA[m][t][3] = sB1[c + 1];
                }
            n >>= 1;
        }
        if (ph == 4) {             // epilogue 1
            #pragma unroll
            for (int m = 0; m < 2; ++m)
                #pragma unroll
                for (int t = 0; t < 8; ++t) {
                    int c = nq * 64 + t * 8 + qc;
                    int r = wr + m * 16 + qr;
                    __nv_bfloat162 hi2, lo2;
                    split2(lrelu(accA[m][t][0]), lrelu(accA[m][t][1]), hi2, lo2);
                    *(__nv_bfloat162*)(sm + SA_HI + r * 528 + c * 2) = hi2;
                    *(__nv_bfloat162*)(sm + SA_LO + r * 528 + c * 2) = lo2;
                    split2(lrelu(accA[m][t][2]), lrelu(accA[m][t][3]), hi2, lo2);
                    *(__nv_bfloat162*)(sm + SA_HI + (r + 8) * 528 + c * 2) = hi2;
                    *(__nv_bfloat162*)(sm + SA_LO + (r + 8) * 528 + c * 2) = lo2;
                }
            #pragma unroll
            for (int m = 0; m < 2; ++m)
                #pragma unroll
                for (int t = 0; t < 4; ++t) {
                    int c = nq * 32 + t * 8 + qc;
                    accB[m][t][0] = sB2[c]; accB[m][t][1] = sB2[c + 1];
                    accB[m][t][2] = sB2[c]; accB[m][t][3] = sB2[c + 1];
                }
        }

        if (g + 1 < GT) { CP_WAIT(1); } else { CP_WAIT(0); }
        __syncthreads();

        const uint32_t slot = wbase + (uint32_t)(g & 1) * 67584u;
        const int kb = (ph < 4 ? ph : ph - 4) * 64;

        #pragma unroll
        for (int j = 0; j < 4; ++j) {
            const int k0 = kb + j * 16;
            unsigned ah[2][4], al[2][4];
            ldsm4(ah[0], aH0 + (uint32_t)(k0 + lcol8) * 2);
            ldsm4(ah[1], aH1 + (uint32_t)(k0 + lcol8) * 2);
            ldsm4(al[0], aL0 + (uint32_t)(k0 + lcol8) * 2);
            ldsm4(al[1], aL1 + (uint32_t)(k0 + lcol8) * 2);
            if (ph < 4) {
                uint32_t brow = slot + (uint32_t)(j * 16 + lrow) * 528;
                #pragma unroll
                for (int p = 0; p < 4; ++p) {
                    int nb = nq * 64 + p * 16;
                    unsigned bh[4], bl[4];
                    ldsm4t(bh, brow + (uint32_t)(nb + lcol8) * 2);
                    ldsm4t(bl, brow + 33792 + (uint32_t)(nb + lcol8) * 2);
                    #pragma unroll
                    for (int m = 0; m < 2; ++m) {
                        mma_bf16(accA[m][2 * p],     ah[m], bh);
                        mma_bf16(accA[m][2 * p + 1], ah[m], bh + 2);
                        mma_bf16(accA[m][2 * p],     al[m], bh);
                        mma_bf16(accA[m][2 * p + 1], al[m], bh + 2);
                        mma_bf16(accA[m][2 * p],     ah[m], bl);
                        mma_bf16(accA[m][2 * p + 1], ah[m], bl + 2);
                    }
                }
            } else {
                uint32_t brow = slot + (uint32_t)(j * 16 + lrow) * 272;
                #pragma unroll
                for (int p = 0; p < 2; ++p) {
                    int nb = nq * 32 + p * 16;
                    unsigned bh[4], bl[4];
                    ldsm4t(bh, brow + (uint32_t)(nb + lcol8) * 2);
                    ldsm4t(bl, brow + 17408 + (uint32_t)(nb + lcol8) * 2);
                    #pragma unroll
                    for (int m = 0; m < 2; ++m) {
                        mma_bf16(accB[m][2 * p],     ah[m], bh);
                        mma_bf16(accB[m][2 * p + 1], ah[m], bh + 2);
                        mma_bf16(accB[m][2 * p],     al[m], bh);
                        mma_bf16(accB[m][2 * p + 1], al[m], bh + 2);
                        mma_bf16(accB[m][2 * p],     ah[m], bl);
                        mma_bf16(accB[m][2 * p + 1], ah[m], bl + 2);
                    }
                }
            }
        }
        __syncthreads();
        if (g + 2 < GT) load_slab64((g + 2) & 7, wbase, tid);
    }

    // level 0 (root)
    #pragma unroll
    for (int m = 0; m < 2; ++m)
        #pragma unroll
        for (int t = 0; t < 4; ++t) {
            int c = nq * 32 + t * 8 + qc;
            #pragma unroll
            for (int h = 0; h < 2; ++h) {
                int r = wr + m * 16 + qr + h * 8;
                if (r < 1)
                    *reinterpret_cast<float2*>(out + (size_t)r * 128 + c) =
                        make_float2(lrelu(accB[m][t][2 * h]), lrelu(accB[m][t][2 * h + 1]));
            }
        }
}

extern "C" void kernel_launch(void* const* d_in, const int* in_sizes, int n_in,
                              void* d_out, int out_size)
{
    const float* leaf = (const float*)d_in[0];
    const float* We   = (const float*)d_in[1];
    const float* be   = (const float*)d_in[2];
    const float* W1   = (const float*)d_in[3];
    const float* b1   = (const float*)d_in[4];
    const float* W2   = (const float*)d_in[5];
    const float* b2   = (const float*)d_in[6];
    float* out = (float*)d_out;

    cudaFuncSetAttribute(level_kernel<true>,  cudaFuncAttributeMaxDynamicSharedMemorySize, SMEM_LVL);
    cudaFuncSetAttribute(level_kernel<false>, cudaFuncAttributeMaxDynamicSharedMemorySize, SMEM_LVL);
    cudaFuncSetAttribute(small_kernel, cudaFuncAttributeMaxDynamicSharedMemorySize, SMEM_SMALL);
    cudaFuncSetAttribute(tail_kernel,  cudaFuncAttributeMaxDynamicSharedMemorySize, SMEM_SMALL);

    prep_kernel<<<256, 256>>>(W1, W2, We);

    const size_t leaf_start = (size_t)(1u << DEPTH) - 1;
    float* Yemb = out + leaf_start * 128;

    for (int l = DEPTH - 1; l >= 7; --l) {
        const int n = 1 << l;
        const size_t p0 = (size_t)(1u << l) - 1;
        float* Y = out + p0 * 128;
        const int grid = (n + 63) / 64;
        if (l == DEPTH - 1) {
            level_kernel<true><<<grid, 256, SMEM_LVL>>>(leaf, Y, Yemb, b1, b2, be, n);
        } else if (l >= 14) {
            const float* X = out + (2 * p0 + 1) * 128;
            level_kernel<false><<<grid, 256, SMEM_LVL>>>(X, Y, Yemb, b1, b2, be, n);
        } else {
            const float* X = out + (2 * p0 + 1) * 128;
            small_kernel<<<grid, 256, SMEM_SMALL>>>(X, Y, b1, b2, n);
        }
    }
    tail_kernel<<<1, 256, SMEM_SMALL>>>(out, b1, b2);
}